// round 4
// baseline (speedup 1.0000x reference)
#include <cuda_runtime.h>

#define SEQ 43
#define DIM 18
#define NLAYERS 6
#define HEADS 3
#define DKH 6
#define DFF 2048
#define BATCH 256
#define AMAX 128
#define NB 7
#define NROWS (BATCH*SEQ)   /* 11008 = 43*256 */
#define LNEPS 1e-6f

#define FSPLIT 16
#define FS (DFF/FSPLIT)      /* 128 = one staging pass */

typedef unsigned long long ull;

__device__ float g_bufA[NROWS*DIM];
__device__ float g_bufB[NROWS*DIM];

__device__ __forceinline__ ull pk2(float lo, float hi){
    ull r; asm("mov.b64 %0, {%1,%2};" : "=l"(r) : "f"(lo), "f"(hi)); return r;
}
__device__ __forceinline__ ull dup2(float v){
    ull r; asm("mov.b64 %0, {%1,%1};" : "=l"(r) : "f"(v)); return r;
}
__device__ __forceinline__ ull fma2(ull a, ull b, ull c){
    ull d; asm("fma.rn.f32x2 %0, %1, %2, %3;" : "=l"(d) : "l"(a), "l"(b), "l"(c)); return d;
}
__device__ __forceinline__ void unpk(ull v, float& lo, float& hi){
    asm("mov.b64 {%0,%1}, %2;" : "=f"(lo), "=f"(hi) : "l"(v));
}

// ---------------------------------------------------------------------------
// Kernel 1: per-layer  y = x + Attn(LN1(x)); y written to BOTH outA and outB.
// outB becomes the residual base that ff_kernel atomically accumulates into.
// ---------------------------------------------------------------------------
__global__ __launch_bounds__(256) void attn_kernel(
    const float* __restrict__ x_in,
    float* __restrict__ outA, float* __restrict__ outB,
    const float* __restrict__ Wq, const float* __restrict__ bq,
    const float* __restrict__ Wk, const float* __restrict__ bk,
    const float* __restrict__ Wv, const float* __restrict__ bv,
    const float* __restrict__ Wo, const float* __restrict__ bo,
    const float* __restrict__ ln_a, const float* __restrict__ ln_b,
    const int* __restrict__ mask, int layer)
{
    __shared__ float xs[SEQ*DIM], x2[SEQ*DIM];
    __shared__ float qs[SEQ*DIM], ks[SEQ*DIM], vs[SEQ*DIM], os[SEQ*DIM];
    __shared__ float sc[HEADS*SEQ*SEQ];
    __shared__ float w[4][DIM*DIM];
    __shared__ float bb[4][DIM];
    __shared__ float lna[DIM], lnb[DIM];

    const int b = blockIdx.x, tid = threadIdx.x;
    const int woff = layer*DIM*DIM;
    for (int i = tid; i < DIM*DIM; i += 256){
        w[0][i] = Wq[woff+i]; w[1][i] = Wk[woff+i];
        w[2][i] = Wv[woff+i]; w[3][i] = Wo[woff+i];
    }
    if (tid < DIM){
        bb[0][tid] = bq[layer*DIM+tid]; bb[1][tid] = bk[layer*DIM+tid];
        bb[2][tid] = bv[layer*DIM+tid]; bb[3][tid] = bo[layer*DIM+tid];
        lna[tid] = ln_a[layer*DIM+tid]; lnb[tid] = ln_b[layer*DIM+tid];
    }
    for (int i = tid; i < SEQ*DIM; i += 256) xs[i] = x_in[b*SEQ*DIM + i];
    __syncthreads();

    // LN1 (std with ddof=1, eps added to sd)
    if (tid < SEQ){
        const float* xr = &xs[tid*DIM];
        float mu = 0.f;
        #pragma unroll
        for (int k = 0; k < DIM; k++) mu += xr[k];
        mu *= (1.f/DIM);
        float var = 0.f;
        #pragma unroll
        for (int k = 0; k < DIM; k++){ float d = xr[k]-mu; var += d*d; }
        float sd = sqrtf(var * (1.f/(DIM-1)));
        float inv = 1.f/(sd + LNEPS);
        #pragma unroll
        for (int k = 0; k < DIM; k++) x2[tid*DIM+k] = lna[k]*(xr[k]-mu)*inv + lnb[k];
    }
    __syncthreads();

    // Q,K,V projections
    for (int idx = tid; idx < 3*SEQ*DIM; idx += 256){
        int wsel = idx/(SEQ*DIM);
        int rc = idx - wsel*SEQ*DIM;
        int r = rc/DIM, c = rc - r*DIM;
        float acc = bb[wsel][c];
        const float* wm = w[wsel];
        #pragma unroll
        for (int k = 0; k < DIM; k++) acc += x2[r*DIM+k]*wm[k*DIM+c];
        (wsel==0 ? qs : (wsel==1 ? ks : vs))[rc] = acc;
    }
    __syncthreads();

    // scores + mask
    const float scale = rsqrtf((float)DKH);
    for (int idx = tid; idx < HEADS*SEQ*SEQ; idx += 256){
        int h = idx/(SEQ*SEQ);
        int st = idx - h*SEQ*SEQ;
        int s = st/SEQ, t = st - s*SEQ;
        float acc = 0.f;
        #pragma unroll
        for (int d = 0; d < DKH; d++) acc += qs[s*DIM+h*DKH+d]*ks[t*DIM+h*DKH+d];
        acc *= scale;
        if (mask[b*SEQ + t] == 0) acc = -1e9f;
        sc[idx] = acc;
    }
    __syncthreads();

    // softmax over t
    if (tid < HEADS*SEQ){
        float* row = &sc[tid*SEQ];
        float m = -1e30f;
        for (int t = 0; t < SEQ; t++) m = fmaxf(m, row[t]);
        float s = 0.f;
        for (int t = 0; t < SEQ; t++){ float e = expf(row[t]-m); row[t] = e; s += e; }
        float inv = 1.f/s;
        for (int t = 0; t < SEQ; t++) row[t] *= inv;
    }
    __syncthreads();

    // attn @ V
    for (int idx = tid; idx < SEQ*DIM; idx += 256){
        int r = idx/DIM, j = idx - r*DIM;
        int h = j/DKH;
        const float* prow = &sc[(h*SEQ + r)*SEQ];
        float acc = 0.f;
        for (int t = 0; t < SEQ; t++) acc += prow[t]*vs[t*DIM+j];
        os[idx] = acc;
    }
    __syncthreads();

    // O projection + residual, dual write
    for (int idx = tid; idx < SEQ*DIM; idx += 256){
        int r = idx/DIM, c = idx - r*DIM;
        float acc = xs[idx] + bb[3][c];
        #pragma unroll
        for (int k = 0; k < DIM; k++) acc += os[r*DIM+k]*w[3][k*DIM+c];
        outA[b*SEQ*DIM + idx] = acc;
        outB[b*SEQ*DIM + idx] = acc;
    }
}

// ---------------------------------------------------------------------------
// Kernel 2: per-layer  x_acc += FF(LN2(x_in))  (x_acc pre-initialized = x_in
// by attn's dual write).  grid (43 row-blocks, 16 f-splits), 128 threads.
// Lane owns 2 rows.  fi processed in groups of 4 with LDS.128 weight loads;
// all math as packed fma.rn.f32x2.
// ---------------------------------------------------------------------------
__global__ __launch_bounds__(128) void ff_kernel(
    const float* __restrict__ x_in, float* __restrict__ x_acc,
    const float* __restrict__ W1g, const float* __restrict__ b1g,
    const float* __restrict__ W2g, const float* __restrict__ b2g,
    const float* __restrict__ ln_a, const float* __restrict__ ln_b, int layer)
{
    __shared__ __align__(16) float sW1[DIM][FS];   // [k][f]
    __shared__ __align__(16) float sW2p[FS][20];   // [f][d], padded to 20 for 16B rows
    __shared__ __align__(16) float sb1[FS];
    __shared__ float sLa[DIM], sLb[DIM];

    const int tid = threadIdx.x;
    const int warp = tid >> 5, lane = tid & 31;
    const int m0 = blockIdx.x*256 + warp*64 + lane;
    const int m1 = m0 + 32;
    const int fb = blockIdx.y * FS;

    if (tid < DIM){ sLa[tid] = ln_a[layer*DIM+tid]; sLb[tid] = ln_b[layer*DIM+tid]; }

    // stage weights
    for (int i = tid; i < DIM*FS; i += 128){
        int k = i/FS, f = i - k*FS;
        sW1[k][f] = W1g[layer*DIM*DFF + k*DFF + fb + f];
    }
    for (int i = tid; i < FS*DIM; i += 128){
        int f = i/DIM, d = i - f*DIM;
        sW2p[f][d] = W2g[layer*DFF*DIM + (fb+f)*DIM + d];
    }
    if (tid < FS) sb1[tid] = b1g[layer*DFF + fb + tid];
    __syncthreads();

    // load rows, LayerNorm, pack to f32x2 duplicates
    ull a0p[DIM], a1p[DIM];
    {
        float xr[DIM];
        #pragma unroll
        for (int k2 = 0; k2 < DIM/2; k2++){
            float2 t = *reinterpret_cast<const float2*>(&x_in[m0*DIM + 2*k2]);
            xr[2*k2] = t.x; xr[2*k2+1] = t.y;
        }
        float mu = 0.f;
        #pragma unroll
        for (int k = 0; k < DIM; k++) mu += xr[k];
        mu *= (1.f/DIM);
        float var = 0.f;
        #pragma unroll
        for (int k = 0; k < DIM; k++){ float d = xr[k]-mu; var += d*d; }
        float inv = 1.f/(sqrtf(var*(1.f/(DIM-1))) + LNEPS);
        #pragma unroll
        for (int k = 0; k < DIM; k++) a0p[k] = dup2(sLa[k]*(xr[k]-mu)*inv + sLb[k]);

        #pragma unroll
        for (int k2 = 0; k2 < DIM/2; k2++){
            float2 t = *reinterpret_cast<const float2*>(&x_in[m1*DIM + 2*k2]);
            xr[2*k2] = t.x; xr[2*k2+1] = t.y;
        }
        mu = 0.f;
        #pragma unroll
        for (int k = 0; k < DIM; k++) mu += xr[k];
        mu *= (1.f/DIM);
        var = 0.f;
        #pragma unroll
        for (int k = 0; k < DIM; k++){ float d = xr[k]-mu; var += d*d; }
        inv = 1.f/(sqrtf(var*(1.f/(DIM-1))) + LNEPS);
        #pragma unroll
        for (int k = 0; k < DIM; k++) a1p[k] = dup2(sLa[k]*(xr[k]-mu)*inv + sLb[k]);
    }

    // y accumulators (9 packed pairs per row); split 0 carries b2 for BOTH rows
    ull y0[DIM/2], y1[DIM/2];
    #pragma unroll
    for (int d2 = 0; d2 < DIM/2; d2++){
        if (blockIdx.y == 0){
            float blo = __ldg(&b2g[layer*DIM + 2*d2]);
            float bhi = __ldg(&b2g[layer*DIM + 2*d2 + 1]);
            y0[d2] = pk2(blo, bhi);
            y1[d2] = pk2(blo, bhi);
        } else {
            y0[d2] = pk2(0.f, 0.f);
            y1[d2] = pk2(0.f, 0.f);
        }
    }

    for (int fi = 0; fi < FS; fi += 4){
        // ---- h for 4 f-values x 2 rows (LDS.128 per k) ----
        float4 b4 = *reinterpret_cast<const float4*>(&sb1[fi]);
        ull h00 = pk2(b4.x, b4.y), h01 = pk2(b4.z, b4.w);
        ull h10 = h00, h11 = h01;
        #pragma unroll
        for (int k = 0; k < DIM; k++){
            ulonglong2 wv = *reinterpret_cast<const ulonglong2*>(&sW1[k][fi]);
            h00 = fma2(a0p[k], wv.x, h00);
            h01 = fma2(a0p[k], wv.y, h01);
            h10 = fma2(a1p[k], wv.x, h10);
            h11 = fma2(a1p[k], wv.y, h11);
        }
        float v0,v1,v2,v3,v4,v5,v6,v7;
        unpk(h00, v0, v1); unpk(h01, v2, v3);
        unpk(h10, v4, v5); unpk(h11, v6, v7);
        v0 = fmaxf(v0,0.f); v1 = fmaxf(v1,0.f); v2 = fmaxf(v2,0.f); v3 = fmaxf(v3,0.f);
        v4 = fmaxf(v4,0.f); v5 = fmaxf(v5,0.f); v6 = fmaxf(v6,0.f); v7 = fmaxf(v7,0.f);

        // ---- y += h * W2 row, per f value ----
        float hv0[4] = {v0,v1,v2,v3};
        float hv1[4] = {v4,v5,v6,v7};
        #pragma unroll
        for (int q = 0; q < 4; q++){
            ull hr0 = dup2(hv0[q]);
            ull hr1 = dup2(hv1[q]);
            const float* w2r = &sW2p[fi+q][0];
            // 18 floats = 4x LDS.128 + 1x LDS.64
            #pragma unroll
            for (int p = 0; p < 4; p++){
                ulonglong2 w2 = *reinterpret_cast<const ulonglong2*>(&w2r[4*p]);
                y0[2*p]   = fma2(hr0, w2.x, y0[2*p]);
                y0[2*p+1] = fma2(hr0, w2.y, y0[2*p+1]);
                y1[2*p]   = fma2(hr1, w2.x, y1[2*p]);
                y1[2*p+1] = fma2(hr1, w2.y, y1[2*p+1]);
            }
            ull w2t = *reinterpret_cast<const ull*>(&w2r[16]);
            y0[8] = fma2(hr0, w2t, y0[8]);
            y1[8] = fma2(hr1, w2t, y1[8]);
        }
    }

    // accumulate partial FF output into the residual buffer
    #pragma unroll
    for (int d2 = 0; d2 < DIM/2; d2++){
        float lo, hi;
        unpk(y0[d2], lo, hi);
        atomicAdd(&x_acc[m0*DIM + 2*d2], lo);
        atomicAdd(&x_acc[m0*DIM + 2*d2 + 1], hi);
        unpk(y1[d2], lo, hi);
        atomicAdd(&x_acc[m1*DIM + 2*d2], lo);
        atomicAdd(&x_acc[m1*DIM + 2*d2 + 1], hi);
    }
}

// ---------------------------------------------------------------------------
// Kernel 3: final head. One block per batch element, 256 threads.
// red = x @ ll2W + ll2b ; R rows on the fly ; P/Q via warp butterflies ;
// out[b,i,j,c] = P[i,c] + (Q[j,c] + flb[c])  with STG.128 writes.
// ---------------------------------------------------------------------------
__global__ __launch_bounds__(256) void final_kernel(
    const float* __restrict__ x,
    const float* __restrict__ ll2W, const float* __restrict__ ll2b,
    const float* __restrict__ llW,  const float* __restrict__ llb,
    const float* __restrict__ flW,  const float* __restrict__ flb,
    float* __restrict__ out)
{
    __shared__ float xb[SEQ*DIM];
    __shared__ float sll2W[DIM*AMAX];
    __shared__ float sllW[SEQ*AMAX];
    __shared__ float redw[8][SEQ+1];
    __shared__ __align__(16) float Ps[AMAX*NB];
    __shared__ __align__(16) float Qs[AMAX*NB];
    __shared__ __align__(16) float QF[AMAX*NB];
    __shared__ float sflb[NB];

    const int b = blockIdx.x, tid = threadIdx.x;
    const int w = tid >> 5, lane = tid & 31;

    for (int i = tid; i < SEQ*DIM; i += 256) xb[i] = x[b*SEQ*DIM + i];
    for (int i = tid; i < DIM*AMAX; i += 256) sll2W[i] = ll2W[i];
    for (int i = tid; i < SEQ*AMAX; i += 256) sllW[i] = llW[i];
    if (tid < NB) sflb[tid] = flb[tid];

    // per-lane constants for its 4 columns j = lane + 32*t4
    float w1r[4][NB], w2r[4][NB], llbr[4];
    #pragma unroll
    for (int t4 = 0; t4 < 4; t4++){
        int j = lane + 32*t4;
        llbr[t4] = __ldg(&llb[j]);
        #pragma unroll
        for (int c = 0; c < NB; c++){
            w1r[t4][c] = __ldg(&flW[j*NB + c]);
            w2r[t4][c] = __ldg(&flW[(AMAX + j)*NB + c]);
        }
    }
    __syncthreads();

    for (int t = 0; t < AMAX/8; t++){
        const int i = t*8 + w;
        {
            float bias = __ldg(&ll2b[i]);
            int s0 = lane;
            if (s0 < SEQ){
                float a = bias;
                #pragma unroll
                for (int k = 0; k < DIM; k++) a += xb[s0*DIM+k]*sll2W[k*AMAX+i];
                redw[w][s0] = a;
            }
            int s1 = lane + 32;
            if (s1 < SEQ){
                float a = bias;
                #pragma unroll
                for (int k = 0; k < DIM; k++) a += xb[s1*DIM+k]*sll2W[k*AMAX+i];
                redw[w][s1] = a;
            }
        }
        __syncwarp();

        float pc[NB], qc[NB];
        #pragma unroll
        for (int c = 0; c < NB; c++){ pc[c] = 0.f; qc[c] = 0.f; }
        #pragma unroll
        for (int t4 = 0; t4 < 4; t4++){
            int j = lane + 32*t4;
            float r = llbr[t4];
            for (int s = 0; s < SEQ; s++) r += redw[w][s]*sllW[s*AMAX + j];
            #pragma unroll
            for (int c = 0; c < NB; c++){
                pc[c] += r*w1r[t4][c];
                qc[c] += r*w2r[t4][c];
            }
        }
        #pragma unroll
        for (int off = 16; off; off >>= 1){
            #pragma unroll
            for (int c = 0; c < NB; c++){
                pc[c] += __shfl_xor_sync(0xffffffffu, pc[c], off);
                qc[c] += __shfl_xor_sync(0xffffffffu, qc[c], off);
            }
        }
        if (lane == 0){
            #pragma unroll
            for (int c = 0; c < NB; c++){ Ps[i*NB+c] = pc[c]; Qs[i*NB+c] = qc[c]; }
        }
        __syncwarp();
    }
    __syncthreads();

    // QF[j*7+c] = Q[j,c] + flb[c]
    for (int i = tid; i < AMAX*NB; i += 256) QF[i] = Qs[i] + sflb[i % NB];
    __syncthreads();

    // vectorized broadcast-sum output write: 896 floats per i-row (÷4 exactly)
    float4* out4 = reinterpret_cast<float4*>(out + (size_t)b * (AMAX*AMAX*NB));
    const int NV = AMAX*AMAX*NB/4;     /* 28672 */
    const int VPI = AMAX*NB/4;         /* 224 float4 per i-row */
    for (int idx4 = tid; idx4 < NV; idx4 += 256){
        int i = idx4 / VPI;
        int rem4 = (idx4 - i*VPI) * 4;
        float4 q = *reinterpret_cast<const float4*>(&QF[rem4]);
        const float* Pi = &Ps[i*NB];
        int c = rem4 % NB;
        q.x += Pi[c];       c++; if (c == NB) c = 0;
        q.y += Pi[c];       c++; if (c == NB) c = 0;
        q.z += Pi[c];       c++; if (c == NB) c = 0;
        q.w += Pi[c];
        out4[idx4] = q;
    }
}

// ---------------------------------------------------------------------------
extern "C" void kernel_launch(void* const* d_in, const int* in_sizes, int n_in,
                              void* d_out, int out_size)
{
    const float *src, *Wq, *bq, *Wk, *bk, *Wv, *bv, *Wo, *bo;
    const float *ln1a, *ln1b, *ln2a, *ln2b, *ffW1, *ffb1, *ffW2, *ffb2;
    const float *ll2W, *ll2b, *llW, *llb, *flW, *flb;
    const int* mask;

    if (in_sizes[1] == NROWS){
        // setup_inputs dict order: src, mask, max_atoms, enc_*..., ll2_*, ll_*, fl_*
        src  = (const float*)d_in[0];
        mask = (const int*)  d_in[1];
        Wq   = (const float*)d_in[3];  bq   = (const float*)d_in[4];
        Wk   = (const float*)d_in[5];  bk   = (const float*)d_in[6];
        Wv   = (const float*)d_in[7];  bv   = (const float*)d_in[8];
        Wo   = (const float*)d_in[9];  bo   = (const float*)d_in[10];
        ln1a = (const float*)d_in[11]; ln1b = (const float*)d_in[12];
        ln2a = (const float*)d_in[13]; ln2b = (const float*)d_in[14];
        ffW1 = (const float*)d_in[15]; ffb1 = (const float*)d_in[16];
        ffW2 = (const float*)d_in[17]; ffb2 = (const float*)d_in[18];
        ll2W = (const float*)d_in[19]; ll2b = (const float*)d_in[20];
        llW  = (const float*)d_in[21]; llb  = (const float*)d_in[22];
        flW  = (const float*)d_in[23]; flb  = (const float*)d_in[24];
    } else {
        // reference() signature order
        src  = (const float*)d_in[0];
        Wq   = (const float*)d_in[1];  bq   = (const float*)d_in[2];
        Wk   = (const float*)d_in[3];  bk   = (const float*)d_in[4];
        Wv   = (const float*)d_in[5];  bv   = (const float*)d_in[6];
        Wo   = (const float*)d_in[7];  bo   = (const float*)d_in[8];
        ln1a = (const float*)d_in[9];  ln1b = (const float*)d_in[10];
        ln2a = (const float*)d_in[11]; ln2b = (const float*)d_in[12];
        ffW1 = (const float*)d_in[13]; ffb1 = (const float*)d_in[14];
        ffW2 = (const float*)d_in[15]; ffb2 = (const float*)d_in[16];
        ll2W = (const float*)d_in[17]; ll2b = (const float*)d_in[18];
        llW  = (const float*)d_in[19]; llb  = (const float*)d_in[20];
        flW  = (const float*)d_in[21]; flb  = (const float*)d_in[22];
        mask = (const int*)  d_in[23];
    }

    float *A, *B;
    cudaGetSymbolAddress((void**)&A, g_bufA);
    cudaGetSymbolAddress((void**)&B, g_bufB);

    const float* cur = src;
    for (int l = 0; l < NLAYERS; l++){
        // attn writes x+attn to BOTH A (ff input) and B (ff residual base)
        attn_kernel<<<BATCH, 256>>>(cur, A, B, Wq, bq, Wk, bk, Wv, bv, Wo, bo,
                                    ln1a, ln1b, mask, l);
        ff_kernel<<<dim3(43, FSPLIT), 128>>>(A, B, ffW1, ffb1, ffW2, ffb2,
                                             ln2a, ln2b, l);
        cur = B;
        float* tmp = A; A = B; B = tmp;   // next attn reads cur(=old B), scratch = old A
    }

    final_kernel<<<BATCH, 256>>>(cur, ll2W, ll2b, llW, llb, flW, flb,
                                 (float*)d_out);
}

// round 5
// speedup vs baseline: 1.2029x; 1.2029x over previous
#include <cuda_runtime.h>

#define SEQ 43
#define DIM 18
#define NLAYERS 6
#define HEADS 3
#define DKH 6
#define DFF 2048
#define BATCH 256
#define AMAX 128
#define NB 7
#define NROWS (BATCH*SEQ)   /* 11008 = 43*256 */
#define LNEPS 1e-6f

#define FSPLIT 8
#define FCHUNK (DFF/FSPLIT)  /* 256 */
#define FS 128               /* smem sub-chunk of f */

typedef unsigned long long ull;

__device__ float g_bufA[NROWS*DIM];
__device__ float g_bufB[NROWS*DIM];

__device__ __forceinline__ ull pk2(float lo, float hi){
    ull r; asm("mov.b64 %0, {%1,%2};" : "=l"(r) : "f"(lo), "f"(hi)); return r;
}
__device__ __forceinline__ ull dup2(float v){
    ull r; asm("mov.b64 %0, {%1,%1};" : "=l"(r) : "f"(v)); return r;
}
__device__ __forceinline__ ull fma2(ull a, ull b, ull c){
    ull d; asm("fma.rn.f32x2 %0, %1, %2, %3;" : "=l"(d) : "l"(a), "l"(b), "l"(c)); return d;
}
__device__ __forceinline__ void unpk(ull v, float& lo, float& hi){
    asm("mov.b64 {%0,%1}, %2;" : "=f"(lo), "=f"(hi) : "l"(v));
}

// ---------------------------------------------------------------------------
// Kernel 1: per-layer  y = x + Attn(LN1(x)); y written to BOTH outA and outB.
// 512 threads/block; mask folded to smem addend; __expf; ILP'd inner loops.
// ---------------------------------------------------------------------------
__global__ __launch_bounds__(512) void attn_kernel(
    const float* __restrict__ x_in,
    float* __restrict__ outA, float* __restrict__ outB,
    const float* __restrict__ Wq, const float* __restrict__ bq,
    const float* __restrict__ Wk, const float* __restrict__ bk,
    const float* __restrict__ Wv, const float* __restrict__ bv,
    const float* __restrict__ Wo, const float* __restrict__ bo,
    const float* __restrict__ ln_a, const float* __restrict__ ln_b,
    const int* __restrict__ mask, int layer)
{
    __shared__ float xs[SEQ*DIM], x2[SEQ*DIM];
    __shared__ float qs[SEQ*DIM], ks[SEQ*DIM], vs[SEQ*DIM], os[SEQ*DIM];
    __shared__ float sc[HEADS*SEQ*SEQ];
    __shared__ float w[4][DIM*DIM];
    __shared__ float bb[4][DIM];
    __shared__ float lna[DIM], lnb[DIM];
    __shared__ float maskadd[SEQ];

    const int b = blockIdx.x, tid = threadIdx.x;
    const int woff = layer*DIM*DIM;
    for (int i = tid; i < DIM*DIM; i += 512){
        w[0][i] = Wq[woff+i]; w[1][i] = Wk[woff+i];
        w[2][i] = Wv[woff+i]; w[3][i] = Wo[woff+i];
    }
    if (tid < DIM){
        bb[0][tid] = bq[layer*DIM+tid]; bb[1][tid] = bk[layer*DIM+tid];
        bb[2][tid] = bv[layer*DIM+tid]; bb[3][tid] = bo[layer*DIM+tid];
        lna[tid] = ln_a[layer*DIM+tid]; lnb[tid] = ln_b[layer*DIM+tid];
    }
    for (int i = tid; i < SEQ*DIM; i += 512) xs[i] = x_in[b*SEQ*DIM + i];
    if (tid >= 64 && tid < 64+SEQ){
        int t = tid - 64;
        maskadd[t] = (mask[b*SEQ + t] == 0) ? -1e9f : 0.f;
    }
    __syncthreads();

    // LN1 (std with ddof=1, eps added to sd)
    if (tid < SEQ){
        const float* xr = &xs[tid*DIM];
        float mu = 0.f;
        #pragma unroll
        for (int k = 0; k < DIM; k++) mu += xr[k];
        mu *= (1.f/DIM);
        float var = 0.f;
        #pragma unroll
        for (int k = 0; k < DIM; k++){ float d = xr[k]-mu; var += d*d; }
        float sd = sqrtf(var * (1.f/(DIM-1)));
        float inv = 1.f/(sd + LNEPS);
        #pragma unroll
        for (int k = 0; k < DIM; k++) x2[tid*DIM+k] = lna[k]*(xr[k]-mu)*inv + lnb[k];
    }
    __syncthreads();

    // Q,K,V projections (2 partial accumulator chains)
    for (int idx = tid; idx < 3*SEQ*DIM; idx += 512){
        int wsel = idx/(SEQ*DIM);
        int rc = idx - wsel*SEQ*DIM;
        int r = rc/DIM, c = rc - r*DIM;
        const float* wm = &w[wsel][c];
        const float* xr = &x2[r*DIM];
        float a0 = bb[wsel][c], a1 = 0.f;
        #pragma unroll
        for (int k = 0; k < DIM; k += 2){
            a0 += xr[k]  *wm[k*DIM];
            a1 += xr[k+1]*wm[(k+1)*DIM];
        }
        (wsel==0 ? qs : (wsel==1 ? ks : vs))[rc] = a0 + a1;
    }
    __syncthreads();

    // scores (mask addend from smem, scale folded)
    const float scale = rsqrtf((float)DKH);
    for (int idx = tid; idx < HEADS*SEQ*SEQ; idx += 512){
        int h = idx/(SEQ*SEQ);
        int st = idx - h*SEQ*SEQ;
        int s = st/SEQ, t = st - s*SEQ;
        const float* qp = &qs[s*DIM + h*DKH];
        const float* kp = &ks[t*DIM + h*DKH];
        float a0 = qp[0]*kp[0] + qp[2]*kp[2] + qp[4]*kp[4];
        float a1 = qp[1]*kp[1] + qp[3]*kp[3] + qp[5]*kp[5];
        sc[idx] = (a0 + a1)*scale + maskadd[t];
    }
    __syncthreads();

    // softmax over t (fast exp, 2-way unrolled)
    if (tid < HEADS*SEQ){
        float* row = &sc[tid*SEQ];
        float m0 = -1e30f, m1 = -1e30f;
        #pragma unroll 2
        for (int t = 0; t < SEQ-1; t += 2){ m0 = fmaxf(m0, row[t]); m1 = fmaxf(m1, row[t+1]); }
        float m = fmaxf(fmaxf(m0, m1), row[SEQ-1]);
        float s0 = 0.f, s1 = 0.f;
        #pragma unroll 2
        for (int t = 0; t < SEQ-1; t += 2){
            float e0 = __expf(row[t]-m);
            float e1 = __expf(row[t+1]-m);
            row[t] = e0; row[t+1] = e1;
            s0 += e0; s1 += e1;
        }
        float el = __expf(row[SEQ-1]-m);
        row[SEQ-1] = el;
        float inv = 1.f/(s0 + s1 + el);
        for (int t = 0; t < SEQ; t++) row[t] *= inv;
    }
    __syncthreads();

    // attn @ V (2 partial accumulators)
    for (int idx = tid; idx < SEQ*DIM; idx += 512){
        int r = idx/DIM, j = idx - r*DIM;
        int h = j/DKH;
        const float* prow = &sc[(h*SEQ + r)*SEQ];
        const float* vp = &vs[j];
        float a0 = 0.f, a1 = 0.f;
        #pragma unroll 2
        for (int t = 0; t < SEQ-1; t += 2){
            a0 += prow[t]  *vp[t*DIM];
            a1 += prow[t+1]*vp[(t+1)*DIM];
        }
        os[idx] = a0 + a1 + prow[SEQ-1]*vp[(SEQ-1)*DIM];
    }
    __syncthreads();

    // O projection + residual, dual write
    for (int idx = tid; idx < SEQ*DIM; idx += 512){
        int r = idx/DIM, c = idx - r*DIM;
        const float* wp = &w[3][c];
        const float* op = &os[r*DIM];
        float a0 = xs[idx] + bb[3][c], a1 = 0.f;
        #pragma unroll
        for (int k = 0; k < DIM; k += 2){
            a0 += op[k]  *wp[k*DIM];
            a1 += op[k+1]*wp[(k+1)*DIM];
        }
        float acc = a0 + a1;
        outA[b*SEQ*DIM + idx] = acc;
        outB[b*SEQ*DIM + idx] = acc;
    }
}

// ---------------------------------------------------------------------------
// Kernel 2 (R3-proven structure): x_acc += FF(LN2(x_in)); x_acc pre-init = x_in
// by attn's dual write. grid (43, 8), 128 threads, lane owns 2 rows, f32x2 FMAs.
// ---------------------------------------------------------------------------
__global__ __launch_bounds__(128) void ff_kernel(
    const float* __restrict__ x_in, float* __restrict__ x_acc,
    const float* __restrict__ W1g, const float* __restrict__ b1g,
    const float* __restrict__ W2g, const float* __restrict__ b2g,
    const float* __restrict__ ln_a, const float* __restrict__ ln_b, int layer)
{
    __shared__ __align__(16) float sW1[DIM][FS];
    __shared__ __align__(16) float sW2[FS*DIM];
    __shared__ __align__(16) float sb1[FS];
    __shared__ float sLa[DIM], sLb[DIM];

    const int tid = threadIdx.x;
    const int warp = tid >> 5, lane = tid & 31;
    const int m0 = blockIdx.x*256 + warp*64 + lane;
    const int m1 = m0 + 32;

    if (tid < DIM){ sLa[tid] = ln_a[layer*DIM+tid]; sLb[tid] = ln_b[layer*DIM+tid]; }
    __syncthreads();

    // load rows, LayerNorm, pack to f32x2 duplicates
    ull a0p[DIM], a1p[DIM];
    {
        float xr[DIM];
        #pragma unroll
        for (int k2 = 0; k2 < DIM/2; k2++){
            float2 t = *reinterpret_cast<const float2*>(&x_in[m0*DIM + 2*k2]);
            xr[2*k2] = t.x; xr[2*k2+1] = t.y;
        }
        float mu = 0.f;
        #pragma unroll
        for (int k = 0; k < DIM; k++) mu += xr[k];
        mu *= (1.f/DIM);
        float var = 0.f;
        #pragma unroll
        for (int k = 0; k < DIM; k++){ float d = xr[k]-mu; var += d*d; }
        float inv = 1.f/(sqrtf(var*(1.f/(DIM-1))) + LNEPS);
        #pragma unroll
        for (int k = 0; k < DIM; k++) a0p[k] = dup2(sLa[k]*(xr[k]-mu)*inv + sLb[k]);

        #pragma unroll
        for (int k2 = 0; k2 < DIM/2; k2++){
            float2 t = *reinterpret_cast<const float2*>(&x_in[m1*DIM + 2*k2]);
            xr[2*k2] = t.x; xr[2*k2+1] = t.y;
        }
        mu = 0.f;
        #pragma unroll
        for (int k = 0; k < DIM; k++) mu += xr[k];
        mu *= (1.f/DIM);
        var = 0.f;
        #pragma unroll
        for (int k = 0; k < DIM; k++){ float d = xr[k]-mu; var += d*d; }
        inv = 1.f/(sqrtf(var*(1.f/(DIM-1))) + LNEPS);
        #pragma unroll
        for (int k = 0; k < DIM; k++) a1p[k] = dup2(sLa[k]*(xr[k]-mu)*inv + sLb[k]);
    }

    // y accumulators; split 0 carries b2 for BOTH rows
    ull y0[DIM/2], y1[DIM/2];
    #pragma unroll
    for (int d2 = 0; d2 < DIM/2; d2++){
        if (blockIdx.y == 0){
            float blo = __ldg(&b2g[layer*DIM + 2*d2]);
            float bhi = __ldg(&b2g[layer*DIM + 2*d2 + 1]);
            y0[d2] = pk2(blo, bhi);
            y1[d2] = pk2(blo, bhi);
        } else {
            y0[d2] = pk2(0.f, 0.f);
            y1[d2] = pk2(0.f, 0.f);
        }
    }

    const int fbase = blockIdx.y * FCHUNK;
    for (int sub = 0; sub < FCHUNK/FS; sub++){
        const int fb = fbase + sub*FS;
        for (int i = tid; i < DIM*FS; i += 128){
            int k = i/FS, f = i - k*FS;
            sW1[k][f] = W1g[layer*DIM*DFF + k*DFF + fb + f];
        }
        for (int i = tid; i < FS*DIM; i += 128)
            sW2[i] = W2g[layer*DFF*DIM + fb*DIM + i];
        if (tid < FS) sb1[tid] = b1g[layer*DFF + fb + tid];
        __syncthreads();

        for (int fi = 0; fi < FS; fi += 2){
            ull h0 = *reinterpret_cast<const ull*>(&sb1[fi]);
            ull h1 = h0;
            #pragma unroll
            for (int k = 0; k < DIM; k++){
                ull wp = *reinterpret_cast<const ull*>(&sW1[k][fi]);
                h0 = fma2(a0p[k], wp, h0);
                h1 = fma2(a1p[k], wp, h1);
            }
            float p,q,r,s;
            unpk(h0, p, q); unpk(h1, r, s);
            p = fmaxf(p, 0.f); q = fmaxf(q, 0.f);
            r = fmaxf(r, 0.f); s = fmaxf(s, 0.f);
            ull pd = dup2(p), qd = dup2(q), rd = dup2(r), sd = dup2(s);
            #pragma unroll
            for (int d2 = 0; d2 < DIM/2; d2++){
                ull w20 = *reinterpret_cast<const ull*>(&sW2[fi*DIM + 2*d2]);
                ull w21 = *reinterpret_cast<const ull*>(&sW2[(fi+1)*DIM + 2*d2]);
                y0[d2] = fma2(pd, w20, y0[d2]);
                y0[d2] = fma2(qd, w21, y0[d2]);
                y1[d2] = fma2(rd, w20, y1[d2]);
                y1[d2] = fma2(sd, w21, y1[d2]);
            }
        }
        __syncthreads();
    }

    // accumulate partial FF output into the residual buffer
    #pragma unroll
    for (int d2 = 0; d2 < DIM/2; d2++){
        float lo, hi;
        unpk(y0[d2], lo, hi);
        atomicAdd(&x_acc[m0*DIM + 2*d2], lo);
        atomicAdd(&x_acc[m0*DIM + 2*d2 + 1], hi);
        unpk(y1[d2], lo, hi);
        atomicAdd(&x_acc[m1*DIM + 2*d2], lo);
        atomicAdd(&x_acc[m1*DIM + 2*d2 + 1], hi);
    }
}

// ---------------------------------------------------------------------------
// Kernel 3: final head. One block per batch element, 256 threads.
// red on the fly ; P/Q via warp butterflies ; float4 broadcast-sum writes.
// ---------------------------------------------------------------------------
__global__ __launch_bounds__(256) void final_kernel(
    const float* __restrict__ x,
    const float* __restrict__ ll2W, const float* __restrict__ ll2b,
    const float* __restrict__ llW,  const float* __restrict__ llb,
    const float* __restrict__ flW,  const float* __restrict__ flb,
    float* __restrict__ out)
{
    __shared__ float xb[SEQ*DIM];
    __shared__ float sll2W[DIM*AMAX];
    __shared__ float sllW[SEQ*AMAX];
    __shared__ float redw[8][SEQ+1];
    __shared__ __align__(16) float Ps[AMAX*NB];
    __shared__ __align__(16) float Qs[AMAX*NB];
    __shared__ __align__(16) float QF[AMAX*NB];
    __shared__ float sflb[NB];

    const int b = blockIdx.x, tid = threadIdx.x;
    const int w = tid >> 5, lane = tid & 31;

    for (int i = tid; i < SEQ*DIM; i += 256) xb[i] = x[b*SEQ*DIM + i];
    for (int i = tid; i < DIM*AMAX; i += 256) sll2W[i] = ll2W[i];
    for (int i = tid; i < SEQ*AMAX; i += 256) sllW[i] = llW[i];
    if (tid < NB) sflb[tid] = flb[tid];

    float w1r[4][NB], w2r[4][NB], llbr[4];
    #pragma unroll
    for (int t4 = 0; t4 < 4; t4++){
        int j = lane + 32*t4;
        llbr[t4] = __ldg(&llb[j]);
        #pragma unroll
        for (int c = 0; c < NB; c++){
            w1r[t4][c] = __ldg(&flW[j*NB + c]);
            w2r[t4][c] = __ldg(&flW[(AMAX + j)*NB + c]);
        }
    }
    __syncthreads();

    for (int t = 0; t < AMAX/8; t++){
        const int i = t*8 + w;
        {
            float bias = __ldg(&ll2b[i]);
            int s0 = lane;
            if (s0 < SEQ){
                float a = bias;
                #pragma unroll
                for (int k = 0; k < DIM; k++) a += xb[s0*DIM+k]*sll2W[k*AMAX+i];
                redw[w][s0] = a;
            }
            int s1 = lane + 32;
            if (s1 < SEQ){
                float a = bias;
                #pragma unroll
                for (int k = 0; k < DIM; k++) a += xb[s1*DIM+k]*sll2W[k*AMAX+i];
                redw[w][s1] = a;
            }
        }
        __syncwarp();

        float pc[NB], qc[NB];
        #pragma unroll
        for (int c = 0; c < NB; c++){ pc[c] = 0.f; qc[c] = 0.f; }
        #pragma unroll
        for (int t4 = 0; t4 < 4; t4++){
            int j = lane + 32*t4;
            float r = llbr[t4];
            for (int s = 0; s < SEQ; s++) r += redw[w][s]*sllW[s*AMAX + j];
            #pragma unroll
            for (int c = 0; c < NB; c++){
                pc[c] += r*w1r[t4][c];
                qc[c] += r*w2r[t4][c];
            }
        }
        #pragma unroll
        for (int off = 16; off; off >>= 1){
            #pragma unroll
            for (int c = 0; c < NB; c++){
                pc[c] += __shfl_xor_sync(0xffffffffu, pc[c], off);
                qc[c] += __shfl_xor_sync(0xffffffffu, qc[c], off);
            }
        }
        if (lane == 0){
            #pragma unroll
            for (int c = 0; c < NB; c++){ Ps[i*NB+c] = pc[c]; Qs[i*NB+c] = qc[c]; }
        }
        __syncwarp();
    }
    __syncthreads();

    for (int i = tid; i < AMAX*NB; i += 256) QF[i] = Qs[i] + sflb[i % NB];
    __syncthreads();

    float4* out4 = reinterpret_cast<float4*>(out + (size_t)b * (AMAX*AMAX*NB));
    const int NV = AMAX*AMAX*NB/4;
    const int VPI = AMAX*NB/4;
    for (int idx4 = tid; idx4 < NV; idx4 += 256){
        int i = idx4 / VPI;
        int rem4 = (idx4 - i*VPI) * 4;
        float4 q = *reinterpret_cast<const float4*>(&QF[rem4]);
        const float* Pi = &Ps[i*NB];
        int c = rem4 % NB;
        q.x += Pi[c];       c++; if (c == NB) c = 0;
        q.y += Pi[c];       c++; if (c == NB) c = 0;
        q.z += Pi[c];       c++; if (c == NB) c = 0;
        q.w += Pi[c];
        out4[idx4] = q;
    }
}

// ---------------------------------------------------------------------------
extern "C" void kernel_launch(void* const* d_in, const int* in_sizes, int n_in,
                              void* d_out, int out_size)
{
    const float *src, *Wq, *bq, *Wk, *bk, *Wv, *bv, *Wo, *bo;
    const float *ln1a, *ln1b, *ln2a, *ln2b, *ffW1, *ffb1, *ffW2, *ffb2;
    const float *ll2W, *ll2b, *llW, *llb, *flW, *flb;
    const int* mask;

    if (in_sizes[1] == NROWS){
        src  = (const float*)d_in[0];
        mask = (const int*)  d_in[1];
        Wq   = (const float*)d_in[3];  bq   = (const float*)d_in[4];
        Wk   = (const float*)d_in[5];  bk   = (const float*)d_in[6];
        Wv   = (const float*)d_in[7];  bv   = (const float*)d_in[8];
        Wo   = (const float*)d_in[9];  bo   = (const float*)d_in[10];
        ln1a = (const float*)d_in[11]; ln1b = (const float*)d_in[12];
        ln2a = (const float*)d_in[13]; ln2b = (const float*)d_in[14];
        ffW1 = (const float*)d_in[15]; ffb1 = (const float*)d_in[16];
        ffW2 = (const float*)d_in[17]; ffb2 = (const float*)d_in[18];
        ll2W = (const float*)d_in[19]; ll2b = (const float*)d_in[20];
        llW  = (const float*)d_in[21]; llb  = (const float*)d_in[22];
        flW  = (const float*)d_in[23]; flb  = (const float*)d_in[24];
    } else {
        src  = (const float*)d_in[0];
        Wq   = (const float*)d_in[1];  bq   = (const float*)d_in[2];
        Wk   = (const float*)d_in[3];  bk   = (const float*)d_in[4];
        Wv   = (const float*)d_in[5];  bv   = (const float*)d_in[6];
        Wo   = (const float*)d_in[7];  bo   = (const float*)d_in[8];
        ln1a = (const float*)d_in[9];  ln1b = (const float*)d_in[10];
        ln2a = (const float*)d_in[11]; ln2b = (const float*)d_in[12];
        ffW1 = (const float*)d_in[13]; ffb1 = (const float*)d_in[14];
        ffW2 = (const float*)d_in[15]; ffb2 = (const float*)d_in[16];
        ll2W = (const float*)d_in[17]; ll2b = (const float*)d_in[18];
        llW  = (const float*)d_in[19]; llb  = (const float*)d_in[20];
        flW  = (const float*)d_in[21]; flb  = (const float*)d_in[22];
        mask = (const int*)  d_in[23];
    }

    float *A, *B;
    cudaGetSymbolAddress((void**)&A, g_bufA);
    cudaGetSymbolAddress((void**)&B, g_bufB);

    const float* cur = src;
    for (int l = 0; l < NLAYERS; l++){
        attn_kernel<<<BATCH, 512>>>(cur, A, B, Wq, bq, Wk, bk, Wv, bv, Wo, bo,
                                    ln1a, ln1b, mask, l);
        ff_kernel<<<dim3(43, FSPLIT), 128>>>(A, B, ffW1, ffb1, ffW2, ffb2,
                                             ln2a, ln2b, l);
        cur = B;
        float* tmp = A; A = B; B = tmp;
    }

    final_kernel<<<BATCH, 256>>>(cur, ll2W, ll2b, llW, llb, flW, flb,
                                 (float*)d_out);
}